// round 2
// baseline (speedup 1.0000x reference)
#include <cuda_runtime.h>
#include <math.h>

#define N_NODES 100000
#define E_EDGES 1600000
// HID = 64, IN = 128, HEADS = 2

// ---------------- scratch (device globals; no allocations allowed) ----------
__device__ float    g_dinv[N_NODES];              // deg -> dinv (in place)
__device__ float    g_h[N_NODES * 64];            // x @ gcn_w
__device__ float    g_acc[N_NODES * 64];          // GCN accumulator -> hg after relu (in place)
__device__ float    g_h2[N_NODES * 128];          // hg @ gat_w  [N, 2 heads, 64]
__device__ float    g_ss[N_NODES * 2];            // score_src per (node, head)
__device__ float    g_sd[N_NODES * 2];            // score_dst per (node, head)
__device__ unsigned g_amax_enc[N_NODES * 2];      // encoded running max
__device__ float    g_amax[N_NODES * 2];          // decoded max
__device__ float    g_denom[N_NODES * 2];         // softmax denominator
__device__ float    g_out_acc[N_NODES * 64];      // GAT accumulator (head-mean folded)

// ---------------- helpers ----------------------------------------------------
__device__ __forceinline__ void red_add_v4(float* addr, float4 v) {
    asm volatile("red.global.add.v4.f32 [%0], {%1, %2, %3, %4};"
                 :: "l"(addr), "f"(v.x), "f"(v.y), "f"(v.z), "f"(v.w)
                 : "memory");
}

__device__ __forceinline__ unsigned encf(float f) {
    unsigned u = __float_as_uint(f);
    return (u & 0x80000000u) ? ~u : (u | 0x80000000u);
}
__device__ __forceinline__ float decf(unsigned u) {
    return (u & 0x80000000u) ? __uint_as_float(u & 0x7fffffffu)
                             : __uint_as_float(~u);
}
__device__ __forceinline__ float leaky(float a) {
    return a >= 0.f ? a : 0.2f * a;
}

// ---------------- degree / norm ----------------------------------------------
__global__ void k_deg_init() {
    int t = blockIdx.x * blockDim.x + threadIdx.x;
    if (t < N_NODES) g_dinv[t] = 1.0f;   // self-loop weight 1
}
__global__ void k_deg_edges(const int* __restrict__ dst, const float* __restrict__ ew) {
    int e = blockIdx.x * blockDim.x + threadIdx.x;
    if (e < E_EDGES) atomicAdd(&g_dinv[dst[e]], ew[e]);
}
__global__ void k_dinv() {
    int t = blockIdx.x * blockDim.x + threadIdx.x;
    if (t < N_NODES) g_dinv[t] = rsqrtf(g_dinv[t]);   // deg >= 1 always
}

// ---------------- GEMM1: g_h = x[N,128] @ gcn_w[128,64] ----------------------
// 2 threads per node, 32 cols each. Plain row-major W in smem (2-way LDS
// conflict across the two col-groups; acceptable, GEMM is a minor cost).
__global__ void k_gemm1(const float* __restrict__ x, const float* __restrict__ W) {
    __shared__ float Ws[128 * 64];
    int tid = threadIdx.x;
    for (int i = tid * 4; i < 128 * 64; i += 256 * 4)
        *(float4*)&Ws[i] = *(const float4*)&W[i];
    __syncthreads();
    int node = blockIdx.x * 128 + (tid >> 1);
    if (node >= N_NODES) return;
    int c0 = (tid & 1) * 32;

    float acc[32];
#pragma unroll
    for (int i = 0; i < 32; i++) acc[i] = 0.f;

    const float4* xrow = (const float4*)(x + (size_t)node * 128);
#pragma unroll 1
    for (int k4 = 0; k4 < 32; k4++) {
        float4 xv = __ldg(&xrow[k4]);
#pragma unroll
        for (int kk = 0; kk < 4; kk++) {
            float xs = (kk == 0) ? xv.x : (kk == 1) ? xv.y : (kk == 2) ? xv.z : xv.w;
            int kbase = (k4 * 4 + kk) * 64 + c0;
#pragma unroll
            for (int i4 = 0; i4 < 8; i4++) {
                float4 w = *(const float4*)&Ws[kbase + 4 * i4];
                acc[i4 * 4 + 0] += xs * w.x;
                acc[i4 * 4 + 1] += xs * w.y;
                acc[i4 * 4 + 2] += xs * w.z;
                acc[i4 * 4 + 3] += xs * w.w;
            }
        }
    }
    float* hout = &g_h[(size_t)node * 64 + c0];
#pragma unroll
    for (int i4 = 0; i4 < 8; i4++)
        *(float4*)&hout[i4 * 4] =
            make_float4(acc[i4 * 4], acc[i4 * 4 + 1], acc[i4 * 4 + 2], acc[i4 * 4 + 3]);
}

// ---------------- GCN self-loop init + edge aggregation ----------------------
__global__ void k_gcn_self() {
    int t = blockIdx.x * blockDim.x + threadIdx.x;
    if (t >= N_NODES * 16) return;
    int n = t >> 4, q = t & 15;
    float di = g_dinv[n];
    float c = di * di;
    float4 h = *(const float4*)&g_h[(size_t)n * 64 + q * 4];
    *(float4*)&g_acc[(size_t)n * 64 + q * 4] =
        make_float4(c * h.x, c * h.y, c * h.z, c * h.w);
}

__global__ void k_gcn_edges(const int* __restrict__ src, const int* __restrict__ dst,
                            const float* __restrict__ ew) {
    int g = blockIdx.x * blockDim.x + threadIdx.x;
    int e = g >> 4;
    if (e >= E_EDGES) return;
    int t = threadIdx.x & 15;
    int s = __ldg(&src[e]);
    int d = __ldg(&dst[e]);
    float norm = 0.f;
    if (t == 0) norm = g_dinv[s] * __ldg(&ew[e]) * g_dinv[d];
    norm = __shfl_sync(0xffffffffu, norm, 0, 16);
    float4 h = *(const float4*)&g_h[(size_t)s * 64 + t * 4];
    red_add_v4(&g_acc[(size_t)d * 64 + t * 4],
               make_float4(norm * h.x, norm * h.y, norm * h.z, norm * h.w));
}

__global__ void k_gcn_final(const float* __restrict__ b) {
    int t = blockIdx.x * blockDim.x + threadIdx.x;
    if (t >= N_NODES * 16) return;
    int q = t & 15;
    float4 a = *(const float4*)&g_acc[(size_t)t * 4];
    float4 bv = *(const float4*)&b[q * 4];
    a.x = fmaxf(a.x + bv.x, 0.f);
    a.y = fmaxf(a.y + bv.y, 0.f);
    a.z = fmaxf(a.z + bv.z, 0.f);
    a.w = fmaxf(a.w + bv.w, 0.f);
    *(float4*)&g_acc[(size_t)t * 4] = a;    // g_acc is now hg
}

// ---------------- GEMM2: g_h2 = hg[N,64] @ gat_w[64,128] ---------------------
// 4 threads per node, 32 cols each. Plain row-major W in smem (4-way conflict).
__global__ void k_gemm2(const float* __restrict__ W) {
    __shared__ float Ws[64 * 128];
    int tid = threadIdx.x;
    for (int i = tid * 4; i < 64 * 128; i += 256 * 4)
        *(float4*)&Ws[i] = *(const float4*)&W[i];
    __syncthreads();
    int node = blockIdx.x * 64 + (tid >> 2);
    if (node >= N_NODES) return;
    int c0 = (tid & 3) * 32;

    float acc[32];
#pragma unroll
    for (int i = 0; i < 32; i++) acc[i] = 0.f;

    const float4* xrow = (const float4*)(g_acc + (size_t)node * 64);
#pragma unroll 1
    for (int k4 = 0; k4 < 16; k4++) {
        float4 xv = __ldg(&xrow[k4]);
#pragma unroll
        for (int kk = 0; kk < 4; kk++) {
            float xs = (kk == 0) ? xv.x : (kk == 1) ? xv.y : (kk == 2) ? xv.z : xv.w;
            int kbase = (k4 * 4 + kk) * 128 + c0;
#pragma unroll
            for (int i4 = 0; i4 < 8; i4++) {
                float4 w = *(const float4*)&Ws[kbase + 4 * i4];
                acc[i4 * 4 + 0] += xs * w.x;
                acc[i4 * 4 + 1] += xs * w.y;
                acc[i4 * 4 + 2] += xs * w.z;
                acc[i4 * 4 + 3] += xs * w.w;
            }
        }
    }
    float* hout = &g_h2[(size_t)node * 128 + c0];
#pragma unroll
    for (int i4 = 0; i4 < 8; i4++)
        *(float4*)&hout[i4 * 4] =
            make_float4(acc[i4 * 4], acc[i4 * 4 + 1], acc[i4 * 4 + 2], acc[i4 * 4 + 3]);
}

// ---------------- GAT scores + softmax ---------------------------------------
// One warp per node: dot(h2[n,h,:], att_src[h]/att_dst[h]); also init amax with
// the self-loop alpha (every node has a self-loop, so no -inf init needed).
__global__ void k_scores(const float* __restrict__ as, const float* __restrict__ ad) {
    int g = blockIdx.x * blockDim.x + threadIdx.x;
    int n = g >> 5;
    if (n >= N_NODES) return;
    int l = g & 31;
    const float* hr = &g_h2[(size_t)n * 128];
    float h0a = hr[l], h0b = hr[32 + l], h1a = hr[64 + l], h1b = hr[96 + l];
    float s0 = h0a * as[l] + h0b * as[32 + l];
    float d0 = h0a * ad[l] + h0b * ad[32 + l];
    float s1 = h1a * as[64 + l] + h1b * as[96 + l];
    float d1 = h1a * ad[64 + l] + h1b * ad[96 + l];
#pragma unroll
    for (int off = 16; off; off >>= 1) {
        s0 += __shfl_xor_sync(0xffffffffu, s0, off);
        d0 += __shfl_xor_sync(0xffffffffu, d0, off);
        s1 += __shfl_xor_sync(0xffffffffu, s1, off);
        d1 += __shfl_xor_sync(0xffffffffu, d1, off);
    }
    if (l == 0) {
        g_ss[2 * n] = s0;  g_ss[2 * n + 1] = s1;
        g_sd[2 * n] = d0;  g_sd[2 * n + 1] = d1;
        g_amax_enc[2 * n]     = encf(leaky(s0 + d0));
        g_amax_enc[2 * n + 1] = encf(leaky(s1 + d1));
    }
}

__global__ void k_amax_edges(const int* __restrict__ src, const int* __restrict__ dst) {
    int g = blockIdx.x * blockDim.x + threadIdx.x;
    if (g >= 2 * E_EDGES) return;
    int e = g >> 1, h = g & 1;
    int s = __ldg(&src[e]);
    int d = __ldg(&dst[e]);
    float a = leaky(g_ss[2 * s + h] + g_sd[2 * d + h]);
    atomicMax(&g_amax_enc[2 * d + h], encf(a));
}

__global__ void k_soft_init() {
    int t = blockIdx.x * blockDim.x + threadIdx.x;
    if (t >= 2 * N_NODES) return;
    float am = decf(g_amax_enc[t]);
    g_amax[t] = am;
    float a = leaky(g_ss[t] + g_sd[t]);   // self-loop term
    g_denom[t] = expf(a - am);
}

__global__ void k_denom_edges(const int* __restrict__ src, const int* __restrict__ dst) {
    int g = blockIdx.x * blockDim.x + threadIdx.x;
    if (g >= 2 * E_EDGES) return;
    int e = g >> 1, h = g & 1;
    int s = __ldg(&src[e]);
    int d = __ldg(&dst[e]);
    float a = leaky(g_ss[2 * s + h] + g_sd[2 * d + h]);
    atomicAdd(&g_denom[2 * d + h], expf(a - g_amax[2 * d + h]));
}

// ---------------- GAT aggregation (head-mean folded: 64-wide accumulator) ----
__global__ void k_gat_self() {
    int t = blockIdx.x * blockDim.x + threadIdx.x;
    if (t >= N_NODES * 16) return;
    int n = t >> 4, q = t & 15;
    float a0 = leaky(g_ss[2 * n] + g_sd[2 * n]);
    float a1 = leaky(g_ss[2 * n + 1] + g_sd[2 * n + 1]);
    float c0 = expf(a0 - g_amax[2 * n])     / fmaxf(g_denom[2 * n],     1e-16f);
    float c1 = expf(a1 - g_amax[2 * n + 1]) / fmaxf(g_denom[2 * n + 1], 1e-16f);
    const float* hr = &g_h2[(size_t)n * 128];
    float4 f0 = *(const float4*)&hr[q * 4];
    float4 f1 = *(const float4*)&hr[64 + q * 4];
    *(float4*)&g_out_acc[(size_t)n * 64 + q * 4] =
        make_float4(0.5f * (c0 * f0.x + c1 * f1.x),
                    0.5f * (c0 * f0.y + c1 * f1.y),
                    0.5f * (c0 * f0.z + c1 * f1.z),
                    0.5f * (c0 * f0.w + c1 * f1.w));
}

__global__ void k_gat_edges(const int* __restrict__ src, const int* __restrict__ dst) {
    int g = blockIdx.x * blockDim.x + threadIdx.x;
    int e = g >> 4;
    if (e >= E_EDGES) return;
    int t = threadIdx.x & 15;
    int s = __ldg(&src[e]);
    int d = __ldg(&dst[e]);
    float coef = 0.f;
    if (t < 2) {
        float a = leaky(g_ss[2 * s + t] + g_sd[2 * d + t]);
        coef = expf(a - g_amax[2 * d + t]) / fmaxf(g_denom[2 * d + t], 1e-16f);
    }
    float c0 = __shfl_sync(0xffffffffu, coef, 0, 16);
    float c1 = __shfl_sync(0xffffffffu, coef, 1, 16);
    const float* hr = &g_h2[(size_t)s * 128];
    float4 f0 = *(const float4*)&hr[t * 4];
    float4 f1 = *(const float4*)&hr[64 + t * 4];
    red_add_v4(&g_out_acc[(size_t)d * 64 + t * 4],
               make_float4(0.5f * (c0 * f0.x + c1 * f1.x),
                           0.5f * (c0 * f0.y + c1 * f1.y),
                           0.5f * (c0 * f0.z + c1 * f1.z),
                           0.5f * (c0 * f0.w + c1 * f1.w)));
}

__global__ void k_final(const float* __restrict__ b, float* __restrict__ out) {
    int t = blockIdx.x * blockDim.x + threadIdx.x;
    if (t >= N_NODES * 16) return;
    int q = t & 15;
    float4 a = *(const float4*)&g_out_acc[(size_t)t * 4];
    float4 bv = *(const float4*)&b[q * 4];
    *(float4*)&out[(size_t)t * 4] =
        make_float4(fmaxf(a.x + bv.x, 0.f), fmaxf(a.y + bv.y, 0.f),
                    fmaxf(a.z + bv.z, 0.f), fmaxf(a.w + bv.w, 0.f));
}

// ---------------- launch -----------------------------------------------------
extern "C" void kernel_launch(void* const* d_in, const int* in_sizes, int n_in,
                              void* d_out, int out_size) {
    const float* x       = (const float*)d_in[0];
    const int*   ei      = (const int*)d_in[1];
    const float* ew      = (const float*)d_in[2];
    const float* gcn_w   = (const float*)d_in[3];
    const float* gcn_b   = (const float*)d_in[4];
    const float* gat_w   = (const float*)d_in[5];
    const float* att_src = (const float*)d_in[6];
    const float* att_dst = (const float*)d_in[7];
    const float* gat_b   = (const float*)d_in[8];
    float* out = (float*)d_out;
    const int* src = ei;
    const int* dst = ei + E_EDGES;

    const int B = 256;
    // degrees / normalization
    k_deg_init<<<(N_NODES + B - 1) / B, B>>>();
    k_deg_edges<<<(E_EDGES + B - 1) / B, B>>>(dst, ew);
    k_dinv<<<(N_NODES + B - 1) / B, B>>>();
    // GCN
    k_gemm1<<<(N_NODES + 127) / 128, B>>>(x, gcn_w);
    k_gcn_self<<<(N_NODES * 16 + B - 1) / B, B>>>();
    k_gcn_edges<<<(E_EDGES * 16 + B - 1) / B, B>>>(src, dst, ew);
    k_gcn_final<<<(N_NODES * 16 + B - 1) / B, B>>>(gcn_b);
    // GAT
    k_gemm2<<<(N_NODES + 63) / 64, B>>>(gat_w);
    k_scores<<<(N_NODES * 32 + B - 1) / B, B>>>(att_src, att_dst);
    k_amax_edges<<<(2 * E_EDGES + B - 1) / B, B>>>(src, dst);
    k_soft_init<<<(2 * N_NODES + B - 1) / B, B>>>();
    k_denom_edges<<<(2 * E_EDGES + B - 1) / B, B>>>(src, dst);
    k_gat_self<<<(N_NODES * 16 + B - 1) / B, B>>>();
    k_gat_edges<<<(E_EDGES * 16 + B - 1) / B, B>>>(src, dst);
    k_final<<<(N_NODES * 16 + B - 1) / B, B>>>(gat_b, out);
}

// round 3
// speedup vs baseline: 1.6931x; 1.6931x over previous
#include <cuda_runtime.h>
#include <math.h>

#define N_NODES 100000
#define E_EDGES 1600000
// HID = 64, IN = 128, HEADS = 2

// ---------------- scratch (device globals; no allocations allowed) ----------
__device__ float    g_dinv[N_NODES];              // deg -> dinv (in place)
__device__ float    g_h[N_NODES * 64];            // x @ gcn_w
__device__ float    g_acc[N_NODES * 64];          // GCN accumulator -> hg after relu (in place)
__device__ float    g_h2[N_NODES * 128];          // hg @ gat_w  [N, 2 heads, 64]
__device__ float    g_ss[N_NODES * 2];            // score_src per (node, head)
__device__ float    g_sd[N_NODES * 2];            // score_dst per (node, head)
__device__ unsigned g_amax_enc[N_NODES * 2];      // encoded running max
__device__ float    g_amax[N_NODES * 2];          // decoded max
__device__ float    g_denom[N_NODES * 2];         // softmax denominator
__device__ float    g_out_acc[N_NODES * 64];      // GAT accumulator (head-mean folded)

// ---------------- helpers ----------------------------------------------------
__device__ __forceinline__ void red_add_v4(float* addr, float4 v) {
    asm volatile("red.global.add.v4.f32 [%0], {%1, %2, %3, %4};"
                 :: "l"(addr), "f"(v.x), "f"(v.y), "f"(v.z), "f"(v.w)
                 : "memory");
}

__device__ __forceinline__ unsigned encf(float f) {
    unsigned u = __float_as_uint(f);
    return (u & 0x80000000u) ? ~u : (u | 0x80000000u);
}
__device__ __forceinline__ float decf(unsigned u) {
    return (u & 0x80000000u) ? __uint_as_float(u & 0x7fffffffu)
                             : __uint_as_float(~u);
}
__device__ __forceinline__ float leaky(float a) {
    return a >= 0.f ? a : 0.2f * a;
}
__device__ __forceinline__ float elem4(float4 v, int kk) {
    return (kk == 0) ? v.x : (kk == 1) ? v.y : (kk == 2) ? v.z : v.w;
}

// ---------------- degree / norm ----------------------------------------------
__global__ void k_deg_init() {
    int t = blockIdx.x * blockDim.x + threadIdx.x;
    if (t < N_NODES) g_dinv[t] = 1.0f;   // self-loop weight 1
}
__global__ void k_deg_edges(const int* __restrict__ dst, const float* __restrict__ ew) {
    int e = blockIdx.x * blockDim.x + threadIdx.x;
    if (e < E_EDGES) atomicAdd(&g_dinv[dst[e]], ew[e]);
}
__global__ void k_dinv() {
    int t = blockIdx.x * blockDim.x + threadIdx.x;
    if (t < N_NODES) g_dinv[t] = rsqrtf(g_dinv[t]);   // deg >= 1 always
}

// ---------------- GEMM1: g_h = x[N,128] @ gcn_w[128,64] ----------------------
// Register-blocked: each thread computes 4 nodes x 8 cols, so each W smem load
// feeds 4 FFMAs -> FFMA-bound instead of LDS-wavefront-bound.
// Block: 256 thr = 8 col-groups x 32 node-groups(4 nodes) -> 128 nodes/block.
__global__ void k_gemm1(const float* __restrict__ x, const float* __restrict__ W) {
    __shared__ float Ws[128 * 64];
    int tid = threadIdx.x;
    for (int i = tid * 4; i < 128 * 64; i += 256 * 4)
        *(float4*)&Ws[i] = *(const float4*)&W[i];
    __syncthreads();

    int cg = tid & 7;          // col group: cols cg*8 .. cg*8+7
    int ng = tid >> 3;         // node group (0..31)
    int n0 = blockIdx.x * 128 + ng * 4;
    int c0 = cg * 8;

    const float4* xr[4];
    bool valid[4];
#pragma unroll
    for (int i = 0; i < 4; i++) {
        int n = n0 + i;
        valid[i] = (n < N_NODES);
        xr[i] = (const float4*)(x + (size_t)(valid[i] ? n : 0) * 128);
    }

    float acc[4][8];
#pragma unroll
    for (int i = 0; i < 4; i++)
#pragma unroll
        for (int j = 0; j < 8; j++) acc[i][j] = 0.f;

#pragma unroll 1
    for (int k4 = 0; k4 < 32; k4++) {
        float4 xv[4];
#pragma unroll
        for (int i = 0; i < 4; i++) xv[i] = __ldg(&xr[i][k4]);
#pragma unroll
        for (int kk = 0; kk < 4; kk++) {
            const float* wrow = &Ws[(k4 * 4 + kk) * 64 + c0];
            float4 w0 = *(const float4*)&wrow[0];
            float4 w1 = *(const float4*)&wrow[4];
#pragma unroll
            for (int i = 0; i < 4; i++) {
                float xs = elem4(xv[i], kk);
                acc[i][0] += xs * w0.x; acc[i][1] += xs * w0.y;
                acc[i][2] += xs * w0.z; acc[i][3] += xs * w0.w;
                acc[i][4] += xs * w1.x; acc[i][5] += xs * w1.y;
                acc[i][6] += xs * w1.z; acc[i][7] += xs * w1.w;
            }
        }
    }
#pragma unroll
    for (int i = 0; i < 4; i++) {
        if (!valid[i]) continue;
        float* hout = &g_h[(size_t)(n0 + i) * 64 + c0];
        *(float4*)&hout[0] = make_float4(acc[i][0], acc[i][1], acc[i][2], acc[i][3]);
        *(float4*)&hout[4] = make_float4(acc[i][4], acc[i][5], acc[i][6], acc[i][7]);
    }
}

// ---------------- GCN self-loop init + edge aggregation ----------------------
__global__ void k_gcn_self() {
    int t = blockIdx.x * blockDim.x + threadIdx.x;
    if (t >= N_NODES * 16) return;
    int n = t >> 4, q = t & 15;
    float di = g_dinv[n];
    float c = di * di;
    float4 h = *(const float4*)&g_h[(size_t)n * 64 + q * 4];
    *(float4*)&g_acc[(size_t)n * 64 + q * 4] =
        make_float4(c * h.x, c * h.y, c * h.z, c * h.w);
}

__global__ void k_gcn_edges(const int* __restrict__ src, const int* __restrict__ dst,
                            const float* __restrict__ ew) {
    int g = blockIdx.x * blockDim.x + threadIdx.x;
    int e = g >> 4;
    if (e >= E_EDGES) return;
    int t = threadIdx.x & 15;
    int s = __ldg(&src[e]);
    int d = __ldg(&dst[e]);
    float norm = 0.f;
    if (t == 0) norm = g_dinv[s] * __ldg(&ew[e]) * g_dinv[d];
    norm = __shfl_sync(0xffffffffu, norm, 0, 16);
    float4 h = *(const float4*)&g_h[(size_t)s * 64 + t * 4];
    red_add_v4(&g_acc[(size_t)d * 64 + t * 4],
               make_float4(norm * h.x, norm * h.y, norm * h.z, norm * h.w));
}

__global__ void k_gcn_final(const float* __restrict__ b) {
    int t = blockIdx.x * blockDim.x + threadIdx.x;
    if (t >= N_NODES * 16) return;
    int q = t & 15;
    float4 a = *(const float4*)&g_acc[(size_t)t * 4];
    float4 bv = *(const float4*)&b[q * 4];
    a.x = fmaxf(a.x + bv.x, 0.f);
    a.y = fmaxf(a.y + bv.y, 0.f);
    a.z = fmaxf(a.z + bv.z, 0.f);
    a.w = fmaxf(a.w + bv.w, 0.f);
    *(float4*)&g_acc[(size_t)t * 4] = a;    // g_acc is now hg
}

// ---------------- GEMM2: g_h2 = hg[N,64] @ gat_w[64,128] ---------------------
// Register-blocked 4 nodes x 8 cols. Block: 256 thr = 16 col-groups x
// 16 node-groups(4 nodes) -> 64 nodes/block.
__global__ void k_gemm2(const float* __restrict__ W) {
    __shared__ float Ws[64 * 128];
    int tid = threadIdx.x;
    for (int i = tid * 4; i < 64 * 128; i += 256 * 4)
        *(float4*)&Ws[i] = *(const float4*)&W[i];
    __syncthreads();

    int cg = tid & 15;         // cols cg*8 .. cg*8+7
    int ng = tid >> 4;         // node group (0..15)
    int n0 = blockIdx.x * 64 + ng * 4;
    int c0 = cg * 8;

    const float4* xr[4];
    bool valid[4];
#pragma unroll
    for (int i = 0; i < 4; i++) {
        int n = n0 + i;
        valid[i] = (n < N_NODES);
        xr[i] = (const float4*)(g_acc + (size_t)(valid[i] ? n : 0) * 64);
    }

    float acc[4][8];
#pragma unroll
    for (int i = 0; i < 4; i++)
#pragma unroll
        for (int j = 0; j < 8; j++) acc[i][j] = 0.f;

#pragma unroll 1
    for (int k4 = 0; k4 < 16; k4++) {
        float4 xv[4];
#pragma unroll
        for (int i = 0; i < 4; i++) xv[i] = __ldg(&xr[i][k4]);
#pragma unroll
        for (int kk = 0; kk < 4; kk++) {
            const float* wrow = &Ws[(k4 * 4 + kk) * 128 + c0];
            float4 w0 = *(const float4*)&wrow[0];
            float4 w1 = *(const float4*)&wrow[4];
#pragma unroll
            for (int i = 0; i < 4; i++) {
                float xs = elem4(xv[i], kk);
                acc[i][0] += xs * w0.x; acc[i][1] += xs * w0.y;
                acc[i][2] += xs * w0.z; acc[i][3] += xs * w0.w;
                acc[i][4] += xs * w1.x; acc[i][5] += xs * w1.y;
                acc[i][6] += xs * w1.z; acc[i][7] += xs * w1.w;
            }
        }
    }
#pragma unroll
    for (int i = 0; i < 4; i++) {
        if (!valid[i]) continue;
        float* hout = &g_h2[(size_t)(n0 + i) * 128 + c0];
        *(float4*)&hout[0] = make_float4(acc[i][0], acc[i][1], acc[i][2], acc[i][3]);
        *(float4*)&hout[4] = make_float4(acc[i][4], acc[i][5], acc[i][6], acc[i][7]);
    }
}

// ---------------- GAT scores + softmax ---------------------------------------
__global__ void k_scores(const float* __restrict__ as, const float* __restrict__ ad) {
    int g = blockIdx.x * blockDim.x + threadIdx.x;
    int n = g >> 5;
    if (n >= N_NODES) return;
    int l = g & 31;
    const float* hr = &g_h2[(size_t)n * 128];
    float h0a = hr[l], h0b = hr[32 + l], h1a = hr[64 + l], h1b = hr[96 + l];
    float s0 = h0a * as[l] + h0b * as[32 + l];
    float d0 = h0a * ad[l] + h0b * ad[32 + l];
    float s1 = h1a * as[64 + l] + h1b * as[96 + l];
    float d1 = h1a * ad[64 + l] + h1b * ad[96 + l];
#pragma unroll
    for (int off = 16; off; off >>= 1) {
        s0 += __shfl_xor_sync(0xffffffffu, s0, off);
        d0 += __shfl_xor_sync(0xffffffffu, d0, off);
        s1 += __shfl_xor_sync(0xffffffffu, s1, off);
        d1 += __shfl_xor_sync(0xffffffffu, d1, off);
    }
    if (l == 0) {
        g_ss[2 * n] = s0;  g_ss[2 * n + 1] = s1;
        g_sd[2 * n] = d0;  g_sd[2 * n + 1] = d1;
        g_amax_enc[2 * n]     = encf(leaky(s0 + d0));
        g_amax_enc[2 * n + 1] = encf(leaky(s1 + d1));
    }
}

__global__ void k_amax_edges(const int* __restrict__ src, const int* __restrict__ dst) {
    int g = blockIdx.x * blockDim.x + threadIdx.x;
    if (g >= 2 * E_EDGES) return;
    int e = g >> 1, h = g & 1;
    int s = __ldg(&src[e]);
    int d = __ldg(&dst[e]);
    float a = leaky(g_ss[2 * s + h] + g_sd[2 * d + h]);
    atomicMax(&g_amax_enc[2 * d + h], encf(a));
}

__global__ void k_soft_init() {
    int t = blockIdx.x * blockDim.x + threadIdx.x;
    if (t >= 2 * N_NODES) return;
    float am = decf(g_amax_enc[t]);
    g_amax[t] = am;
    float a = leaky(g_ss[t] + g_sd[t]);   // self-loop term
    g_denom[t] = expf(a - am);
}

__global__ void k_denom_edges(const int* __restrict__ src, const int* __restrict__ dst) {
    int g = blockIdx.x * blockDim.x + threadIdx.x;
    if (g >= 2 * E_EDGES) return;
    int e = g >> 1, h = g & 1;
    int s = __ldg(&src[e]);
    int d = __ldg(&dst[e]);
    float a = leaky(g_ss[2 * s + h] + g_sd[2 * d + h]);
    atomicAdd(&g_denom[2 * d + h], expf(a - g_amax[2 * d + h]));
}

// ---------------- GAT aggregation (head-mean folded: 64-wide accumulator) ----
__global__ void k_gat_self() {
    int t = blockIdx.x * blockDim.x + threadIdx.x;
    if (t >= N_NODES * 16) return;
    int n = t >> 4, q = t & 15;
    float a0 = leaky(g_ss[2 * n] + g_sd[2 * n]);
    float a1 = leaky(g_ss[2 * n + 1] + g_sd[2 * n + 1]);
    float c0 = expf(a0 - g_amax[2 * n])     / fmaxf(g_denom[2 * n],     1e-16f);
    float c1 = expf(a1 - g_amax[2 * n + 1]) / fmaxf(g_denom[2 * n + 1], 1e-16f);
    const float* hr = &g_h2[(size_t)n * 128];
    float4 f0 = *(const float4*)&hr[q * 4];
    float4 f1 = *(const float4*)&hr[64 + q * 4];
    *(float4*)&g_out_acc[(size_t)n * 64 + q * 4] =
        make_float4(0.5f * (c0 * f0.x + c1 * f1.x),
                    0.5f * (c0 * f0.y + c1 * f1.y),
                    0.5f * (c0 * f0.z + c1 * f1.z),
                    0.5f * (c0 * f0.w + c1 * f1.w));
}

__global__ void k_gat_edges(const int* __restrict__ src, const int* __restrict__ dst) {
    int g = blockIdx.x * blockDim.x + threadIdx.x;
    int e = g >> 4;
    if (e >= E_EDGES) return;
    int t = threadIdx.x & 15;
    int s = __ldg(&src[e]);
    int d = __ldg(&dst[e]);
    float coef = 0.f;
    if (t < 2) {
        float a = leaky(g_ss[2 * s + t] + g_sd[2 * d + t]);
        coef = expf(a - g_amax[2 * d + t]) / fmaxf(g_denom[2 * d + t], 1e-16f);
    }
    float c0 = __shfl_sync(0xffffffffu, coef, 0, 16);
    float c1 = __shfl_sync(0xffffffffu, coef, 1, 16);
    const float* hr = &g_h2[(size_t)s * 128];
    float4 f0 = *(const float4*)&hr[t * 4];
    float4 f1 = *(const float4*)&hr[64 + t * 4];
    red_add_v4(&g_out_acc[(size_t)d * 64 + t * 4],
               make_float4(0.5f * (c0 * f0.x + c1 * f1.x),
                           0.5f * (c0 * f0.y + c1 * f1.y),
                           0.5f * (c0 * f0.z + c1 * f1.z),
                           0.5f * (c0 * f0.w + c1 * f1.w)));
}

__global__ void k_final(const float* __restrict__ b, float* __restrict__ out) {
    int t = blockIdx.x * blockDim.x + threadIdx.x;
    if (t >= N_NODES * 16) return;
    int q = t & 15;
    float4 a = *(const float4*)&g_out_acc[(size_t)t * 4];
    float4 bv = *(const float4*)&b[q * 4];
    *(float4*)&out[(size_t)t * 4] =
        make_float4(fmaxf(a.x + bv.x, 0.f), fmaxf(a.y + bv.y, 0.f),
                    fmaxf(a.z + bv.z, 0.f), fmaxf(a.w + bv.w, 0.f));
}

// ---------------- launch -----------------------------------------------------
extern "C" void kernel_launch(void* const* d_in, const int* in_sizes, int n_in,
                              void* d_out, int out_size) {
    const float* x       = (const float*)d_in[0];
    const int*   ei      = (const int*)d_in[1];
    const float* ew      = (const float*)d_in[2];
    const float* gcn_w   = (const float*)d_in[3];
    const float* gcn_b   = (const float*)d_in[4];
    const float* gat_w   = (const float*)d_in[5];
    const float* att_src = (const float*)d_in[6];
    const float* att_dst = (const float*)d_in[7];
    const float* gat_b   = (const float*)d_in[8];
    float* out = (float*)d_out;
    const int* src = ei;
    const int* dst = ei + E_EDGES;

    const int B = 256;
    // degrees / normalization
    k_deg_init<<<(N_NODES + B - 1) / B, B>>>();
    k_deg_edges<<<(E_EDGES + B - 1) / B, B>>>(dst, ew);
    k_dinv<<<(N_NODES + B - 1) / B, B>>>();
    // GCN
    k_gemm1<<<(N_NODES + 127) / 128, B>>>(x, gcn_w);
    k_gcn_self<<<(N_NODES * 16 + B - 1) / B, B>>>();
    k_gcn_edges<<<(E_EDGES * 16 + B - 1) / B, B>>>(src, dst, ew);
    k_gcn_final<<<(N_NODES * 16 + B - 1) / B, B>>>(gcn_b);
    // GAT
    k_gemm2<<<(N_NODES + 63) / 64, B>>>(gat_w);
    k_scores<<<(N_NODES * 32 + B - 1) / B, B>>>(att_src, att_dst);
    k_amax_edges<<<(2 * E_EDGES + B - 1) / B, B>>>(src, dst);
    k_soft_init<<<(2 * N_NODES + B - 1) / B, B>>>();
    k_denom_edges<<<(2 * E_EDGES + B - 1) / B, B>>>(src, dst);
    k_gat_self<<<(N_NODES * 16 + B - 1) / B, B>>>();
    k_gat_edges<<<(E_EDGES * 16 + B - 1) / B, B>>>(src, dst);
    k_final<<<(N_NODES * 16 + B - 1) / B, B>>>(gat_b, out);
}